// round 4
// baseline (speedup 1.0000x reference)
#include <cuda_runtime.h>
#include <cuda_bf16.h>
#include <cstdint>

// Problem constants
#define BATCH 32
#define CIN   256
#define COUT  256
#define Hh    56
#define Ww    56
#define NPIX  (Hh*Ww)          // 3136
#define CW    8                // 256 bits = 8 x uint32 words per pixel
#define NVALS 100352.0         // BATCH*NPIX per-channel count
#define BN_EPS 1e-5

// ----------------- scratch (device globals; no allocation) -----------------
__device__ unsigned           g_xbits[BATCH * NPIX * CW];       // [b][p][wd]  3.2 MB
__device__ unsigned           g_wbits[COUT * 9 * CW];           // [co][tap][wd] 73.7 KB
__device__ float              g_alpha[COUT];
__device__ int                g_sum[COUT];
__device__ unsigned long long g_sumsq[COUT];
__device__ float              g_scale[COUT];
__device__ float              g_shift[COUT];
__device__ short              g_S[BATCH * NPIX * COUT];         // [b][p][co] 51.4 MB

// ----------------- kernel 1: zero the stats accumulators -----------------
__global__ void zero_stats_kernel() {
    int t = threadIdx.x;
    if (t < COUT) { g_sum[t] = 0; g_sumsq[t] = 0ull; }
}

// ----------------- kernel 2: weight prep -----------------
// Per co: mean over C_in per tap, clamp, alpha = mean|wc|, sign bits (bit=1 <=> negative).
__global__ void __launch_bounds__(256) prep_w_kernel(const float* __restrict__ w) {
    int co   = blockIdx.x;
    int ci   = threadIdx.x;           // 0..255
    int lane = ci & 31;
    int warp = ci >> 5;               // = word index (ci/32)

    float v[9];
    const float* wp = w + ((size_t)co * CIN + ci) * 9;
#pragma unroll
    for (int t = 0; t < 9; t++) v[t] = wp[t];

    __shared__ float part[8][9];
    __shared__ float tapmean[9];

    // deterministic tree reduction: sum over ci per tap
#pragma unroll
    for (int t = 0; t < 9; t++) {
        float s = v[t];
#pragma unroll
        for (int o = 16; o > 0; o >>= 1) s += __shfl_down_sync(0xffffffffu, s, o);
        if (lane == 0) part[warp][t] = s;
    }
    __syncthreads();
    if (ci < 9) {
        float s = 0.f;
#pragma unroll
        for (int i = 0; i < 8; i++) s += part[i][ci];
        tapmean[ci] = s * (1.0f / 256.0f);
    }
    __syncthreads();

    float asum = 0.f;
#pragma unroll
    for (int t = 0; t < 9; t++) {
        float wc = v[t] - tapmean[t];
        wc = fminf(fmaxf(wc, -1.0f), 1.0f);
        asum += fabsf(wc);
        unsigned m = __ballot_sync(0xffffffffu, wc < 0.0f);
        if (lane == 0) g_wbits[co * 72 + t * CW + warp] = m;
    }
    // reduce asum over block
    __syncthreads();
#pragma unroll
    for (int o = 16; o > 0; o >>= 1) asum += __shfl_down_sync(0xffffffffu, asum, o);
    if (lane == 0) part[warp][0] = asum;
    __syncthreads();
    if (ci == 0) {
        float tot = 0.f;
#pragma unroll
        for (int i = 0; i < 8; i++) tot += part[i][0];
        g_alpha[co] = tot * (1.0f / 2304.0f);
    }
}

// ----------------- kernel 3: binarize x into bit-planes -----------------
// One thread per output word. Word order (b, wd, p) so lanes read consecutive p
// (coalesced 128B loads over the NCHW input). bit k = (x[ci=wd*32+k] < 0).
__global__ void __launch_bounds__(256) binarize_kernel(const float* __restrict__ x) {
    int idx = blockIdx.x * 256 + threadIdx.x;       // 0 .. BATCH*CW*NPIX-1
    if (idx >= BATCH * CW * NPIX) return;
    int p  = idx % NPIX;
    int wd = (idx / NPIX) % CW;
    int b  = idx / (NPIX * CW);

    const float* xp = x + ((size_t)(b * CIN + wd * 32) * NPIX) + p;
    unsigned m = 0u;
#pragma unroll
    for (int k = 0; k < 32; k++) {
        float v = xp[(size_t)k * NPIX];
        m |= (v < 0.0f ? 1u : 0u) << k;
    }
    g_xbits[((size_t)(b * NPIX + p)) * CW + wd] = m;
}

// ----------------- kernel 4: XNOR-popcount conv + per-channel stats -----------------
// Block = (h, b). Thread = co. Weights in registers; x rows in smem, read as LDS.128
// broadcasts. Border taps: smem zero-padded; correct via precomputed weight popcounts:
//   S = 256*nvalid - 2*Ptot + 2*sum_{invalid taps} popc(w_tap)
__global__ void __launch_bounds__(256) conv_kernel() {
    int h  = blockIdx.x;      // 0..55
    int b  = blockIdx.y;      // 0..31
    int co = threadIdx.x;     // 0..255
    int tid = threadIdx.x;

    __shared__ unsigned sx[3][Ww + 2][CW];    // 5.57 KB, zero-padded cols 0 and 57

    // zero everything (covers pad cols + invalid rows)
    for (int i = tid; i < 3 * (Ww + 2) * CW; i += 256) ((unsigned*)sx)[i] = 0u;
    __syncthreads();
    // load valid rows (contiguous, coalesced)
#pragma unroll
    for (int r = 0; r < 3; r++) {
        int gh = h - 1 + r;
        if (gh >= 0 && gh < Hh) {
            const unsigned* src = g_xbits + ((size_t)(b * NPIX + gh * Ww)) * CW;
            unsigned* dst = &sx[r][1][0];
            for (int i = tid; i < Ww * CW; i += 256) dst[i] = src[i];
        }
    }
    __syncthreads();

    // per-thread weights (72 words) via vector loads
    unsigned wreg[72];
    {
        const uint4* wp = (const uint4*)(g_wbits + co * 72);
#pragma unroll
        for (int i = 0; i < 18; i++) {
            uint4 q = wp[i];
            wreg[i * 4 + 0] = q.x; wreg[i * 4 + 1] = q.y;
            wreg[i * 4 + 2] = q.z; wreg[i * 4 + 3] = q.w;
        }
    }
    // per-tap weight popcounts for border corrections
    int nw[9];
#pragma unroll
    for (int t = 0; t < 9; t++) {
        int s = 0;
#pragma unroll
        for (int wd = 0; wd < CW; wd++) s += __popc(wreg[t * CW + wd]);
        nw[t] = s;
    }
    int rowInv = (h == 0) ? 0 : (h == Hh - 1) ? 2 : -1;
    int corrH = 0, nvH = 9;
    if (rowInv >= 0) { corrH = nw[rowInv*3+0] + nw[rowInv*3+1] + nw[rowInv*3+2]; nvH = 6; }
    int nwc0 = nw[0] + nw[3] + nw[6];
    int nwc2 = nw[2] + nw[5] + nw[8];
    int rflag = (rowInv >= 0) ? 1 : 0;

    short* sout = g_S + ((size_t)(b * NPIX + h * Ww)) * COUT + co;
    int lsum = 0, lsq = 0;

    for (int w = 0; w < Ww; w++) {
        int P = 0;
#pragma unroll
        for (int t = 0; t < 9; t++) {
            int r = t / 3, c = t % 3;
            const uint4* xp = (const uint4*)(&sx[r][w + c][0]);
            uint4 xa = xp[0];
            uint4 xb = xp[1];
            P += __popc(xa.x ^ wreg[t*CW+0]) + __popc(xa.y ^ wreg[t*CW+1]);
            P += __popc(xa.z ^ wreg[t*CW+2]) + __popc(xa.w ^ wreg[t*CW+3]);
            P += __popc(xb.x ^ wreg[t*CW+4]) + __popc(xb.y ^ wreg[t*CW+5]);
            P += __popc(xb.z ^ wreg[t*CW+6]) + __popc(xb.w ^ wreg[t*CW+7]);
        }
        int nvalid = nvH, corr = corrH;
        if (w == 0) {
            nvalid = nvH - 3 + rflag;
            corr   = corrH + nwc0 - (rflag ? nw[rowInv*3+0] : 0);
        } else if (w == Ww - 1) {
            nvalid = nvH - 3 + rflag;
            corr   = corrH + nwc2 - (rflag ? nw[rowInv*3+2] : 0);
        }
        int S = 256 * nvalid - 2 * P + 2 * corr;
        sout[(size_t)w * COUT] = (short)S;
        lsum += S;
        lsq  += S * S;           // <= 56*2304^2 = 2.97e8 < INT_MAX
    }
    atomicAdd(&g_sum[co], lsum);
    atomicAdd(&g_sumsq[co], (unsigned long long)(long long)lsq);
}

// ----------------- kernel 5: finalize per-channel thresholds -----------------
__global__ void finalize_kernel(const float* __restrict__ gamma,
                                const float* __restrict__ beta) {
    int co = threadIdx.x;
    if (co >= COUT) return;
    double s    = (double)g_sum[co];
    double sq   = (double)(long long)g_sumsq[co];
    double mean = s / NVALS;
    double var  = sq / NVALS - mean * mean;            // exact var of integer S
    double a    = (double)g_alpha[co];
    double inv  = 1.0 / sqrt(a * a * var + BN_EPS);
    double sc   = (double)gamma[co] * a * inv;
    g_scale[co] = (float)sc;
    g_shift[co] = (float)((double)beta[co] - sc * mean);
}

// ----------------- kernel 6: threshold + transpose [b][p][co] -> [b][co][p] -----------------
__global__ void __launch_bounds__(256) thresh_kernel(float* __restrict__ out) {
    __shared__ float tile[32][33];
    int p0  = blockIdx.x * 32;     // 98 tiles (3136 = 98*32)
    int co0 = blockIdx.y * 32;     // 8 tiles
    int b   = blockIdx.z;
    int tx  = threadIdx.x;         // 0..31
    int ty  = threadIdx.y;         // 0..7

    float sc = g_scale[co0 + tx];
    float sh = g_shift[co0 + tx];
#pragma unroll
    for (int r = 0; r < 4; r++) {
        int pl = ty * 4 + r;
        short s = g_S[((size_t)(b * NPIX + p0 + pl)) * COUT + co0 + tx];
        tile[pl][tx] = (fmaf(sc, (float)s, sh) > 0.0f) ? 1.0f : 0.0f;
    }
    __syncthreads();
#pragma unroll
    for (int r = 0; r < 4; r++) {
        int cl = ty * 4 + r;
        out[((size_t)(b * COUT + co0 + cl)) * NPIX + p0 + tx] = tile[tx][cl];
    }
}

// ----------------- launch -----------------
extern "C" void kernel_launch(void* const* d_in, const int* in_sizes, int n_in,
                              void* d_out, int out_size) {
    const float* x      = (const float*)d_in[0];
    const float* weight = (const float*)d_in[1];
    // const float* bias = (const float*)d_in[2];  // cancels inside BN; unused
    const float* gamma  = (const float*)d_in[3];
    const float* beta   = (const float*)d_in[4];
    float* out = (float*)d_out;

    zero_stats_kernel<<<1, 256>>>();
    prep_w_kernel<<<COUT, 256>>>(weight);
    {
        int nwords = BATCH * CW * NPIX;
        binarize_kernel<<<(nwords + 255) / 256, 256>>>(x);
    }
    conv_kernel<<<dim3(Hh, BATCH), 256>>>();
    finalize_kernel<<<1, 256>>>(gamma, beta);
    thresh_kernel<<<dim3(NPIX / 32, COUT / 32, BATCH), dim3(32, 8)>>>(out);
}